// round 1
// baseline (speedup 1.0000x reference)
#include <cuda_runtime.h>
#include <math.h>

#define T_TOKENS 8192
#define HIDDEN   1024
#define INTER    4096
#define NEXP     8
#define MTILES   136                // 136 * 128 = 17408 >= 16384 + 8*127 worst-case padding
#define MAXP     (MTILES * 128)

// ---------------- scratch (device globals; no allocations allowed) ----------------
__device__ float g_h[(size_t)MAXP * INTER];        // GEMM1 output (silu'd), 285 MB
__device__ float g_pair_out[(size_t)MAXP * HIDDEN];// GEMM2 output (weighted), 71 MB
__device__ int   g_perm[MAXP];                      // pair slot -> token id (-1 = dummy)
__device__ float g_wbuf[MAXP];                      // pair slot -> combine weight
__device__ int   g_pair_slot[T_TOKENS * 2];         // token,k -> slot
__device__ int   g_topi[T_TOKENS * 2];
__device__ float g_topw[T_TOKENS * 2];
__device__ int   g_count_pair[NEXP];
__device__ int   g_count_top1[NEXP];
__device__ float g_probsum[NEXP];
__device__ int   g_offset[NEXP];                    // padded segment start per expert
__device__ int   g_cursor[NEXP];

// ---------------- init: reset counters + dummy-fill perm ----------------
__global__ void init_kernel() {
    int i = blockIdx.x * blockDim.x + threadIdx.x;
    if (i < MAXP) { g_perm[i] = -1; g_wbuf[i] = 0.f; }
    if (i < NEXP) {
        g_count_pair[i] = 0; g_count_top1[i] = 0;
        g_probsum[i] = 0.f;  g_cursor[i] = 0;
    }
}

// ---------------- router: one warp per token ----------------
__global__ void router_kernel(const float* __restrict__ x,
                              const float* __restrict__ rw) {
    int gwarp = (blockIdx.x * blockDim.x + threadIdx.x) >> 5;
    int lane  = threadIdx.x & 31;
    __shared__ float s_prob[NEXP];
    if (threadIdx.x < NEXP) s_prob[threadIdx.x] = 0.f;
    __syncthreads();

    if (gwarp < T_TOKENS) {
        const float* xr = x + (size_t)gwarp * HIDDEN;
        float acc[NEXP];
        #pragma unroll
        for (int e = 0; e < NEXP; e++) acc[e] = 0.f;
        for (int k = lane; k < HIDDEN; k += 32) {
            float xv = xr[k];
            #pragma unroll
            for (int e = 0; e < NEXP; e++)
                acc[e] = fmaf(xv, rw[e * HIDDEN + k], acc[e]);
        }
        #pragma unroll
        for (int e = 0; e < NEXP; e++) {
            #pragma unroll
            for (int off = 16; off; off >>= 1)
                acc[e] += __shfl_xor_sync(0xFFFFFFFFu, acc[e], off);
        }
        // softmax over 8 (all lanes redundantly)
        float m = acc[0];
        #pragma unroll
        for (int e = 1; e < NEXP; e++) m = fmaxf(m, acc[e]);
        float p[NEXP], s = 0.f;
        #pragma unroll
        for (int e = 0; e < NEXP; e++) { p[e] = expf(acc[e] - m); s += p[e]; }
        float inv = 1.f / s;
        #pragma unroll
        for (int e = 0; e < NEXP; e++) p[e] *= inv;
        // top-2, earliest-index tie-break (matches jax top_k)
        int i0 = 0; float v0 = p[0];
        #pragma unroll
        for (int e = 1; e < NEXP; e++) if (p[e] > v0) { v0 = p[e]; i0 = e; }
        int i1 = -1; float v1 = -1.f;
        #pragma unroll
        for (int e = 0; e < NEXP; e++) if (e != i0 && p[e] > v1) { v1 = p[e]; i1 = e; }
        float winv = 1.f / (v0 + v1);
        if (lane == 0) {
            g_topi[2 * gwarp]     = i0;
            g_topi[2 * gwarp + 1] = i1;
            g_topw[2 * gwarp]     = v0 * winv;
            g_topw[2 * gwarp + 1] = v1 * winv;
            atomicAdd(&g_count_top1[i0], 1);
            atomicAdd(&g_count_pair[i0], 1);
            atomicAdd(&g_count_pair[i1], 1);
        }
        if (lane < NEXP) atomicAdd(&s_prob[lane], p[lane]);
    }
    __syncthreads();
    if (threadIdx.x < NEXP) atomicAdd(&g_probsum[threadIdx.x], s_prob[threadIdx.x]);
}

// ---------------- setup: padded offsets + aux loss ----------------
__global__ void setup_kernel(float* __restrict__ out, int out_size) {
    if (threadIdx.x == 0 && blockIdx.x == 0) {
        int off = 0;
        for (int e = 0; e < NEXP; e++) {
            g_offset[e] = off;
            g_cursor[e] = off;
            int pc = ((g_count_pair[e] + 127) / 128) * 128;
            off += pc;
        }
        float aux = 0.f;
        for (int e = 0; e < NEXP; e++)
            aux += ((float)g_count_top1[e] / (float)T_TOKENS) *
                   (g_probsum[e] / (float)T_TOKENS);
        aux *= (float)NEXP;
        if (out_size > T_TOKENS * HIDDEN)
            out[(size_t)T_TOKENS * HIDDEN] = aux;
    }
}

// ---------------- scatter: fill per-expert slot lists ----------------
__global__ void scatter_kernel() {
    int t = blockIdx.x * blockDim.x + threadIdx.x;
    if (t < T_TOKENS) {
        #pragma unroll
        for (int k = 0; k < 2; k++) {
            int e = g_topi[2 * t + k];
            int slot = atomicAdd(&g_cursor[e], 1);
            g_perm[slot] = t;
            g_wbuf[slot] = g_topw[2 * t + k];
            g_pair_slot[2 * t + k] = slot;
        }
    }
}

// ---------------- expert GEMMs: 128x128x16 tiles, 8x8 micro-tile ----------------
__device__ __forceinline__ float silu_f(float v) {
    return v / (1.f + expf(-v));
}

template <bool FIRST>
__global__ void __launch_bounds__(256, 2)
expert_gemm(const float* __restrict__ X, const float* __restrict__ W) {
    const int KTOT = FIRST ? HIDDEN : INTER;   // K dimension
    const int ASTR = FIRST ? HIDDEN : INTER;   // A row stride
    const int BSTR = FIRST ? INTER  : HIDDEN;  // B row stride (== N total)

    __shared__ float As[16][128];
    __shared__ float Bs[16][128];

    const int tileN = blockIdx.x;
    const int tileM = blockIdx.y;
    const int row0  = tileM * 128;

    // expert for this M-segment (segments are 128-aligned)
    int e = 0;
    #pragma unroll
    for (int i = 1; i < NEXP; i++) if (row0 >= g_offset[i]) e = i;

    const float* Bbase = W + (size_t)e * ((size_t)HIDDEN * INTER) + (size_t)tileN * 128;

    const int tid   = threadIdx.x;
    const int a_row = tid >> 2;           // 0..63
    const int a_col = (tid & 3) * 4;      // 0..12
    const int b_row = tid >> 5;           // 0..7
    const int b_col = (tid & 31) * 4;     // 0..124

    const float* aptr[2];
    #pragma unroll
    for (int it = 0; it < 2; it++) {
        int r = a_row + it * 64;
        if (FIRST) {
            int tok = g_perm[row0 + r];
            aptr[it] = (tok >= 0) ? (X + (size_t)tok * ASTR + a_col) : nullptr;
        } else {
            aptr[it] = g_h + (size_t)(row0 + r) * ASTR + a_col;
        }
    }
    const float* bptr = Bbase + (size_t)b_row * BSTR + b_col;

    float acc[8][8];
    #pragma unroll
    for (int i = 0; i < 8; i++)
        #pragma unroll
        for (int j = 0; j < 8; j++) acc[i][j] = 0.f;

    const int tr = tid >> 4;  // 0..15
    const int tc = tid & 15;  // 0..15

    for (int k0 = 0; k0 < KTOT; k0 += 16) {
        #pragma unroll
        for (int it = 0; it < 2; it++) {
            int r = a_row + it * 64;
            float4 v = make_float4(0.f, 0.f, 0.f, 0.f);
            if (!FIRST || aptr[it]) v = *(const float4*)(aptr[it] + k0);
            As[a_col + 0][r] = v.x;
            As[a_col + 1][r] = v.y;
            As[a_col + 2][r] = v.z;
            As[a_col + 3][r] = v.w;
        }
        #pragma unroll
        for (int it = 0; it < 2; it++) {
            float4 v = *(const float4*)(bptr + (size_t)(k0 + it * 8) * BSTR);
            *(float4*)&Bs[b_row + it * 8][b_col] = v;
        }
        __syncthreads();
        #pragma unroll
        for (int k = 0; k < 16; k++) {
            float af[8], bf[8];
            *(float4*)&af[0] = *(const float4*)&As[k][tr * 8];
            *(float4*)&af[4] = *(const float4*)&As[k][tr * 8 + 4];
            *(float4*)&bf[0] = *(const float4*)&Bs[k][tc * 8];
            *(float4*)&bf[4] = *(const float4*)&Bs[k][tc * 8 + 4];
            #pragma unroll
            for (int i = 0; i < 8; i++)
                #pragma unroll
                for (int j = 0; j < 8; j++)
                    acc[i][j] = fmaf(af[i], bf[j], acc[i][j]);
        }
        __syncthreads();
    }

    if (FIRST) {
        #pragma unroll
        for (int i = 0; i < 8; i++) {
            int m = row0 + tr * 8 + i;
            float* orow = g_h + (size_t)m * INTER + (size_t)tileN * 128 + tc * 8;
            #pragma unroll
            for (int j = 0; j < 8; j += 4) {
                float4 v;
                v.x = silu_f(acc[i][j + 0]);
                v.y = silu_f(acc[i][j + 1]);
                v.z = silu_f(acc[i][j + 2]);
                v.w = silu_f(acc[i][j + 3]);
                *(float4*)(orow + j) = v;
            }
        }
    } else {
        #pragma unroll
        for (int i = 0; i < 8; i++) {
            int m = row0 + tr * 8 + i;
            float wmul = g_wbuf[m];
            float* orow = g_pair_out + (size_t)m * HIDDEN + (size_t)tileN * 128 + tc * 8;
            #pragma unroll
            for (int j = 0; j < 8; j += 4) {
                float4 v;
                v.x = wmul * acc[i][j + 0];
                v.y = wmul * acc[i][j + 1];
                v.z = wmul * acc[i][j + 2];
                v.w = wmul * acc[i][j + 3];
                *(float4*)(orow + j) = v;
            }
        }
    }
}

// ---------------- combine: out[t] = pair_out[slot0] + pair_out[slot1] ----------------
__global__ void combine_kernel(float* __restrict__ out) {
    int t = blockIdx.x;
    int s0 = g_pair_slot[2 * t];
    int s1 = g_pair_slot[2 * t + 1];
    const float4* p0 = (const float4*)(g_pair_out + (size_t)s0 * HIDDEN);
    const float4* p1 = (const float4*)(g_pair_out + (size_t)s1 * HIDDEN);
    float4* o = (float4*)(out + (size_t)t * HIDDEN);
    int c = threadIdx.x;  // 256 threads, 256 float4 = 1024 floats
    float4 a = p0[c], b = p1[c];
    o[c] = make_float4(a.x + b.x, a.y + b.y, a.z + b.z, a.w + b.w);
}

// ---------------- launch ----------------
extern "C" void kernel_launch(void* const* d_in, const int* in_sizes, int n_in,
                              void* d_out, int out_size) {
    const float* x  = (const float*)d_in[0];
    const float* rw = (const float*)d_in[1];
    const float* w1 = (const float*)d_in[2];
    const float* w2 = (const float*)d_in[3];
    float* out = (float*)d_out;

    init_kernel<<<(MAXP + 255) / 256, 256>>>();
    router_kernel<<<T_TOKENS / 8, 256>>>(x, rw);
    setup_kernel<<<1, 32>>>(out, out_size);
    scatter_kernel<<<(T_TOKENS + 255) / 256, 256>>>();
    expert_gemm<true ><<<dim3(INTER  / 128, MTILES), 256>>>(x, w1);
    expert_gemm<false><<<dim3(HIDDEN / 128, MTILES), 256>>>(nullptr, w2);
    combine_kernel<<<T_TOKENS, 256>>>(out);
}